// round 5
// baseline (speedup 1.0000x reference)
#include <cuda_runtime.h>
#include <math.h>

#define N_SAMP 1024
#define D      16384
#define WH     128
#define S1     129   // stride (floats) for transposed / S buffers
#define S2     132   // stride (floats) for natural-layout buffers (float4-aligned)

// ---- device scratch (no allocations allowed) ----
__device__ float g_gram[N_SAMP * N_SAMP];
__device__ float g_sq[N_SAMP];
__device__ int   g_hp[N_SAMP];
__device__ int   g_hn[N_SAMP];
__device__ float g_dd[2 * N_SAMP];

// ---------------------------------------------------------------------------
// Kernel 1: row squared norms
// ---------------------------------------------------------------------------
__global__ void sq_kernel(const float* __restrict__ X) {
    int i = blockIdx.x;
    const float4* row = (const float4*)(X + (size_t)i * D);
    float s = 0.f;
    for (int u = threadIdx.x; u < D / 4; u += 256) {
        float4 v = row[u];
        s += v.x * v.x + v.y * v.y + v.z * v.z + v.w * v.w;
    }
    __shared__ float red[256];
    red[threadIdx.x] = s;
    __syncthreads();
    for (int st = 128; st > 0; st >>= 1) {
        if (threadIdx.x < st) red[threadIdx.x] += red[threadIdx.x + st];
        __syncthreads();
    }
    if (threadIdx.x == 0) g_sq[i] = red[0];
}

// ---------------------------------------------------------------------------
// Kernel 2: symmetric Gram GEMM  G = X X^T  (only bi<=bj tiles, mirrored)
// 64x64 tile, BK=16, 256 threads, 4x4 microtile, double-buffered smem.
// ---------------------------------------------------------------------------
#define BK 16
__global__ __launch_bounds__(256, 4)
void gram_kernel(const float* __restrict__ X) {
    // decode triangular block index -> (bi, bj), bi <= bj, 16x16 tile grid
    int r = blockIdx.x, bi = 0;
    while (r >= 16 - bi) { r -= 16 - bi; bi++; }
    int bj = bi + r;

    __shared__ float As[2][BK][68];
    __shared__ float Bs[2][BK][68];

    int tid  = threadIdx.x;
    int ti   = tid >> 4;          // 0..15 (i microtile)
    int tj   = tid & 15;          // 0..15 (j microtile)
    int lrow = tid >> 2;          // 0..63 loader row
    int lc   = (tid & 3) << 2;    // 0,4,8,12 loader col (float4)

    const float* Ap = X + (size_t)(bi * 64 + lrow) * D + lc;
    const float* Bp = X + (size_t)(bj * 64 + lrow) * D + lc;

    float acc[4][4];
#pragma unroll
    for (int m = 0; m < 4; m++)
#pragma unroll
        for (int n = 0; n < 4; n++) acc[m][n] = 0.f;

    float4 fa = *(const float4*)Ap;
    float4 fb = *(const float4*)Bp;
    // stage tile 0 (transposed: As[k][row])
    As[0][lc + 0][lrow] = fa.x; As[0][lc + 1][lrow] = fa.y;
    As[0][lc + 2][lrow] = fa.z; As[0][lc + 3][lrow] = fa.w;
    Bs[0][lc + 0][lrow] = fb.x; Bs[0][lc + 1][lrow] = fb.y;
    Bs[0][lc + 2][lrow] = fb.z; Bs[0][lc + 3][lrow] = fb.w;
    __syncthreads();

    int cur = 0;
    for (int kk = 0; kk < D; kk += BK) {
        bool more = (kk + BK) < D;
        if (more) {
            fa = *(const float4*)(Ap + kk + BK);
            fb = *(const float4*)(Bp + kk + BK);
        }
#pragma unroll
        for (int k = 0; k < BK; k++) {
            float4 av = *(const float4*)&As[cur][k][ti * 4];
            float4 bv = *(const float4*)&Bs[cur][k][tj * 4];
            float a0 = av.x, a1 = av.y, a2 = av.z, a3 = av.w;
            float b0 = bv.x, b1 = bv.y, b2 = bv.z, b3 = bv.w;
            acc[0][0] = fmaf(a0, b0, acc[0][0]); acc[0][1] = fmaf(a0, b1, acc[0][1]);
            acc[0][2] = fmaf(a0, b2, acc[0][2]); acc[0][3] = fmaf(a0, b3, acc[0][3]);
            acc[1][0] = fmaf(a1, b0, acc[1][0]); acc[1][1] = fmaf(a1, b1, acc[1][1]);
            acc[1][2] = fmaf(a1, b2, acc[1][2]); acc[1][3] = fmaf(a1, b3, acc[1][3]);
            acc[2][0] = fmaf(a2, b0, acc[2][0]); acc[2][1] = fmaf(a2, b1, acc[2][1]);
            acc[2][2] = fmaf(a2, b2, acc[2][2]); acc[2][3] = fmaf(a2, b3, acc[2][3]);
            acc[3][0] = fmaf(a3, b0, acc[3][0]); acc[3][1] = fmaf(a3, b1, acc[3][1]);
            acc[3][2] = fmaf(a3, b2, acc[3][2]); acc[3][3] = fmaf(a3, b3, acc[3][3]);
        }
        if (more) {
            int nxt = cur ^ 1;
            As[nxt][lc + 0][lrow] = fa.x; As[nxt][lc + 1][lrow] = fa.y;
            As[nxt][lc + 2][lrow] = fa.z; As[nxt][lc + 3][lrow] = fa.w;
            Bs[nxt][lc + 0][lrow] = fb.x; Bs[nxt][lc + 1][lrow] = fb.y;
            Bs[nxt][lc + 2][lrow] = fb.z; Bs[nxt][lc + 3][lrow] = fb.w;
            __syncthreads();
            cur = nxt;
        }
    }

#pragma unroll
    for (int m = 0; m < 4; m++)
#pragma unroll
        for (int n = 0; n < 4; n++) {
            int i = bi * 64 + ti * 4 + m;
            int j = bj * 64 + tj * 4 + n;
            float v = acc[m][n];
            g_gram[i * N_SAMP + j] = v;
            if (bi != bj) g_gram[j * N_SAMP + i] = v;
        }
}

// ---------------------------------------------------------------------------
// Kernel 3: hard mining (argmax same-id / argmin diff-id of sq[j] - 2 G[i][j])
// ---------------------------------------------------------------------------
__global__ void mine_kernel(const int* __restrict__ targets) {
    int i   = blockIdx.x;
    int tid = threadIdx.x;
    int tg  = targets[i];

    float bpv = -3.0e38f; int bpi = 0;
    float bnv =  3.0e38f; int bni = 0;
    for (int j = tid; j < N_SAMP; j += 256) {
        float val = g_sq[j] - 2.f * g_gram[i * N_SAMP + j];
        if (targets[j] == tg) {
            if (val > bpv || (val == bpv && j < bpi)) { bpv = val; bpi = j; }
        } else {
            if (val < bnv || (val == bnv && j < bni)) { bnv = val; bni = j; }
        }
    }
    __shared__ float spv[256]; __shared__ int spi[256];
    __shared__ float snv[256]; __shared__ int sni[256];
    spv[tid] = bpv; spi[tid] = bpi; snv[tid] = bnv; sni[tid] = bni;
    __syncthreads();
    for (int st = 128; st > 0; st >>= 1) {
        if (tid < st) {
            float ov = spv[tid + st]; int oi = spi[tid + st];
            if (ov > spv[tid] || (ov == spv[tid] && oi < spi[tid])) { spv[tid] = ov; spi[tid] = oi; }
            float nv = snv[tid + st]; int ni2 = sni[tid + st];
            if (nv < snv[tid] || (nv == snv[tid] && ni2 < sni[tid])) { snv[tid] = nv; sni[tid] = ni2; }
        }
        __syncthreads();
    }
    if (tid == 0) { g_hp[i] = spi[0]; g_hn[i] = sni[0]; }
}

// ---------------------------------------------------------------------------
// Kernel 4: per-sample cross-attention alignment + distance.
// One block per (sample, pos/neg). 256 threads, 8x8 microtiles with STRIDED
// lane mapping (i = ty+16m, j = tx+16n) so all smem GEMM reads are
// conflict-free or broadcast.
// ---------------------------------------------------------------------------
__global__ __launch_bounds__(256, 1)
void attn_kernel(const float* __restrict__ X) {
    extern __shared__ float sm[];
    float* b1 = sm;                 // A^T (S1) -> later O natural (S2)
    float* b2 = sm + 128 * S2;      // O^T (S1) -> later exchange / reduce
    float* b3 = sm + 2 * 128 * S2;  // S^T / P^T (S1) -> later M natural (S2)

    const int tid = threadIdx.x;
    const int tx  = tid & 15;
    const int ty  = tid >> 4;
    const int blk = blockIdx.x;
    const int bb  = blk >> 1;
    const int oidx = (blk & 1) ? g_hn[bb] : g_hp[bb];
    const float* Ag = X + (size_t)bb * D;
    const float* Og = X + (size_t)oidx * D;

    // ---- load A^T -> b1, O^T -> b2 (transposed, stride S1) ----
    for (int u = tid; u < 4096; u += 256) {
        int rr = u >> 5;
        int c4 = (u & 31) << 2;
        float4 va = *(const float4*)(Ag + rr * WH + c4);
        float4 vo = *(const float4*)(Og + rr * WH + c4);
        b1[(c4 + 0) * S1 + rr] = va.x; b1[(c4 + 1) * S1 + rr] = va.y;
        b1[(c4 + 2) * S1 + rr] = va.z; b1[(c4 + 3) * S1 + rr] = va.w;
        b2[(c4 + 0) * S1 + rr] = vo.x; b2[(c4 + 1) * S1 + rr] = vo.y;
        b2[(c4 + 2) * S1 + rr] = vo.z; b2[(c4 + 3) * S1 + rr] = vo.w;
    }
    __syncthreads();

    // ---- GEMM1: S[i][j] = sum_c A[i][c] O[j][c], i=ty+16m, j=tx+16n ----
    float acc[8][8];
#pragma unroll
    for (int m = 0; m < 8; m++)
#pragma unroll
        for (int n = 0; n < 8; n++) acc[m][n] = 0.f;

#pragma unroll 2
    for (int c = 0; c < WH; c++) {
        float av[8], bv[8];
#pragma unroll
        for (int m = 0; m < 8; m++) av[m] = b1[c * S1 + ty + 16 * m];
#pragma unroll
        for (int n = 0; n < 8; n++) bv[n] = b2[c * S1 + tx + 16 * n];
#pragma unroll
        for (int m = 0; m < 8; m++)
#pragma unroll
            for (int n = 0; n < 8; n++) acc[m][n] = fmaf(av[m], bv[n], acc[m][n]);
    }
    const float scale = 0.088388347648318447f;  // 1/sqrt(128)
#pragma unroll
    for (int m = 0; m < 8; m++)
#pragma unroll
        for (int n = 0; n < 8; n++)
            b3[(tx + 16 * n) * S1 + (ty + 16 * m)] = acc[m][n] * scale;  // store S^T
    __syncthreads();

    // ---- reload O natural into b1 (stride S2, float4) ----
    for (int u = tid; u < 4096; u += 256) {
        int rr = u >> 5;
        int c4 = (u & 31) << 2;
        float4 vo = *(const float4*)(Og + rr * WH + c4);
        *(float4*)(b1 + rr * S2 + c4) = vo;
    }

    // ---- softmax over rows of S (= columns of b3); 2 threads per column ----
    float* xch = b2;  // b2 free after GEMM1
    const int ci = tid & 127;
    const int j0 = (tid >> 7) * 64;
    float lmax = -3.0e38f;
    for (int j = j0; j < j0 + 64; j++) lmax = fmaxf(lmax, b3[j * S1 + ci]);
    xch[tid] = lmax;
    __syncthreads();
    float gmax = fmaxf(xch[ci], xch[ci + 128]);
    float lsum = 0.f;
    for (int j = j0; j < j0 + 64; j++) {
        float e = __expf(b3[j * S1 + ci] - gmax);
        b3[j * S1 + ci] = e;
        lsum += e;
    }
    __syncthreads();
    xch[tid] = lsum;
    __syncthreads();
    float rinv = 1.f / (xch[ci] + xch[ci + 128]);
    for (int j = j0; j < j0 + 64; j++) b3[j * S1 + ci] *= rinv;
    __syncthreads();  // also orders O reload before GEMM2

    // ---- GEMM2: M[i][c] = sum_j P[i][j] O[j][c]; P^T in b3, O in b1 ----
    float acc2[8][8];
#pragma unroll
    for (int m = 0; m < 8; m++)
#pragma unroll
        for (int n = 0; n < 8; n++) acc2[m][n] = 0.f;

#pragma unroll 2
    for (int j = 0; j < WH; j++) {
        float pv[8], ov[8];
#pragma unroll
        for (int m = 0; m < 8; m++) pv[m] = b3[j * S1 + ty + 16 * m];
#pragma unroll
        for (int n = 0; n < 8; n++) ov[n] = b1[j * S2 + tx + 16 * n];
#pragma unroll
        for (int m = 0; m < 8; m++)
#pragma unroll
            for (int n = 0; n < 8; n++) acc2[m][n] = fmaf(pv[m], ov[n], acc2[m][n]);
    }
    __syncthreads();  // all done reading b3 as P
#pragma unroll
    for (int m = 0; m < 8; m++)
#pragma unroll
        for (int n = 0; n < 8; n++)
            b3[(ty + 16 * m) * S2 + (tx + 16 * n)] = acc2[m][n];  // M natural
    __syncthreads();

    // ---- dist^2 = sum (A - M)^2, coalesced, block reduce ----
    float dsum = 0.f;
    for (int u = tid; u < 4096; u += 256) {
        int rr = u >> 5;
        int c4 = (u & 31) << 2;
        float4 va = *(const float4*)(Ag + rr * WH + c4);
        float4 vm = *(const float4*)(b3 + rr * S2 + c4);
        float dx = va.x - vm.x, dy = va.y - vm.y;
        float dz = va.z - vm.z, dw = va.w - vm.w;
        dsum += dx * dx + dy * dy + dz * dz + dw * dw;
    }
    b2[tid] = dsum;
    __syncthreads();
    for (int st = 128; st > 0; st >>= 1) {
        if (tid < st) b2[tid] += b2[tid + st];
        __syncthreads();
    }
    if (tid == 0) g_dd[blk] = b2[0];
}

// ---------------------------------------------------------------------------
// Kernel 5: final margin ranking loss
// ---------------------------------------------------------------------------
__global__ void loss_kernel(float* __restrict__ out) {
    int tid = threadIdx.x;
    float s = 0.f;
    for (int b = tid; b < N_SAMP; b += 256) {
        float dap = sqrtf(g_dd[2 * b]);
        float dan = sqrtf(g_dd[2 * b + 1]);
        float v = dap - dan + 0.3f;
        s += (v > 0.f) ? v : 0.f;
    }
    __shared__ float red[256];
    red[tid] = s;
    __syncthreads();
    for (int st = 128; st > 0; st >>= 1) {
        if (tid < st) red[tid] += red[tid + st];
        __syncthreads();
    }
    if (tid == 0) out[0] = red[0] * (1.0f / (float)N_SAMP);
}

// ---------------------------------------------------------------------------
extern "C" void kernel_launch(void* const* d_in, const int* in_sizes, int n_in,
                              void* d_out, int out_size) {
    const float* X;
    const int*   T;
    if (n_in >= 2 && in_sizes[0] == N_SAMP && in_sizes[1] != N_SAMP) {
        // defensive: targets first
        T = (const int*)d_in[0];
        X = (const float*)d_in[1];
    } else {
        X = (const float*)d_in[0];
        T = (const int*)d_in[1];
    }

    const int smem_attn = 3 * 128 * S2 * (int)sizeof(float);  // 202752 B
    cudaFuncSetAttribute(attn_kernel, cudaFuncAttributeMaxDynamicSharedMemorySize,
                         smem_attn);

    sq_kernel<<<N_SAMP, 256>>>(X);
    gram_kernel<<<136, 256>>>(X);
    mine_kernel<<<N_SAMP, 256>>>(T);
    attn_kernel<<<2 * N_SAMP, 256, smem_attn>>>(X);
    loss_kernel<<<1, 256>>>((float*)d_out);
}

// round 8
// speedup vs baseline: 1.3212x; 1.3212x over previous
#include <cuda_runtime.h>
#include <math.h>
#include <stdint.h>

#define N_SAMP 1024
#define D      16384
#define WH     128
#define SA     130   // attn natural-layout stride (words); 130 % 4 == 2 -> conflict-free LDS.64
#define SM2    132   // attn M-buffer stride (float4-aligned)
#define GSA    18    // gram stage row stride (words); 18 % 4 == 2 -> conflict-free LDS.64

typedef unsigned long long ull;

// ---- device scratch (no allocations allowed) ----
__device__ float g_gram[N_SAMP * N_SAMP];
__device__ float g_part[144 * 16384];      // split-K partial tiles
__device__ float g_sq[N_SAMP];
__device__ int   g_hp[N_SAMP];
__device__ int   g_hn[N_SAMP];
__device__ float g_dd[2 * N_SAMP];

// ---- packed fp32x2 FMA (Blackwell dual fp32; exact fp32 math) ----
__device__ __forceinline__ void ffma2(ull& d, ull a, ull b) {
    asm("fma.rn.f32x2 %0, %1, %2, %0;" : "+l"(d) : "l"(a), "l"(b));
}
__device__ __forceinline__ float f2sum(ull v) {
    return __uint_as_float((unsigned)(v & 0xFFFFFFFFu)) +
           __uint_as_float((unsigned)(v >> 32));
}

// ===========================================================================
// Kernel 1: row squared norms
// ===========================================================================
__global__ void sq_kernel(const float* __restrict__ X) {
    int i = blockIdx.x;
    const float4* row = (const float4*)(X + (size_t)i * D);
    float s = 0.f;
    for (int u = threadIdx.x; u < D / 4; u += 256) {
        float4 v = row[u];
        s += v.x * v.x + v.y * v.y + v.z * v.z + v.w * v.w;
    }
    __shared__ float red[256];
    red[threadIdx.x] = s;
    __syncthreads();
    for (int st = 128; st > 0; st >>= 1) {
        if (threadIdx.x < st) red[threadIdx.x] += red[threadIdx.x + st];
        __syncthreads();
    }
    if (threadIdx.x == 0) g_sq[i] = red[0];
}

// ===========================================================================
// Kernel 2: Gram GEMM with FFMA2. 36 triangular 128x128 tiles x 4 K-splits
// = 144 blocks (one wave). 256 threads, 8x8 microtile, k-paired dual
// accumulators (exact fp32, summed at the end). BK=16, double-buffered.
// Stage layout: natural rows [128][GSA]; LDS.64 of adjacent k-pairs;
// a-operand broadcast, b-operand lane-stride GSA=18 (conflict-free).
// ===========================================================================
__global__ __launch_bounds__(256, 1)
void gram_f2(const float* __restrict__ X) {
    __shared__ __align__(16) float As[2][128 * GSA];
    __shared__ __align__(16) float Bs[2][128 * GSA];

    const int tid = threadIdx.x;
    const int tx  = tid & 15;       // j  = tx + 16n
    const int ty  = tid >> 4;       // i  = ty + 16m

    int blk = blockIdx.x;
    int split = blk / 36;
    int tile  = blk % 36;
    int r = tile, bi = 0;
    while (r >= 8 - bi) { r -= 8 - bi; bi++; }
    int bj = bi + r;

    const float* Ag = X + (size_t)(bi * 128) * D + split * 4096;
    const float* Bg = X + (size_t)(bj * 128) * D + split * 4096;

    // loader: 512 float4 per matrix per chunk; each thread covers two rows
    const int lr0 = tid >> 2;            // 0..63
    const int lr1 = lr0 + 64;            // 64..127
    const int lc  = (tid & 3) << 2;      // 0,4,8,12

    ull acc[8][8];
#pragma unroll
    for (int m = 0; m < 8; m++)
#pragma unroll
        for (int n = 0; n < 8; n++) acc[m][n] = 0ull;

    float4 pa0 = *(const float4*)(Ag + (size_t)lr0 * D + lc);
    float4 pa1 = *(const float4*)(Ag + (size_t)lr1 * D + lc);
    float4 pb0 = *(const float4*)(Bg + (size_t)lr0 * D + lc);
    float4 pb1 = *(const float4*)(Bg + (size_t)lr1 * D + lc);
    // stage 0 (float2 stores: 8B-aligned for any row at stride 18)
    *(float2*)&As[0][lr0 * GSA + lc]     = make_float2(pa0.x, pa0.y);
    *(float2*)&As[0][lr0 * GSA + lc + 2] = make_float2(pa0.z, pa0.w);
    *(float2*)&As[0][lr1 * GSA + lc]     = make_float2(pa1.x, pa1.y);
    *(float2*)&As[0][lr1 * GSA + lc + 2] = make_float2(pa1.z, pa1.w);
    *(float2*)&Bs[0][lr0 * GSA + lc]     = make_float2(pb0.x, pb0.y);
    *(float2*)&Bs[0][lr0 * GSA + lc + 2] = make_float2(pb0.z, pb0.w);
    *(float2*)&Bs[0][lr1 * GSA + lc]     = make_float2(pb1.x, pb1.y);
    *(float2*)&Bs[0][lr1 * GSA + lc + 2] = make_float2(pb1.z, pb1.w);
    __syncthreads();

    const int NC = 4096 / 16;  // 256 chunks
    int cur = 0;
    for (int c = 0; c < NC; c++) {
        bool more = (c + 1) < NC;
        if (more) {
            int kk = (c + 1) * 16;
            pa0 = *(const float4*)(Ag + (size_t)lr0 * D + kk + lc);
            pa1 = *(const float4*)(Ag + (size_t)lr1 * D + kk + lc);
            pb0 = *(const float4*)(Bg + (size_t)lr0 * D + kk + lc);
            pb1 = *(const float4*)(Bg + (size_t)lr1 * D + kk + lc);
        }
#pragma unroll
        for (int kp = 0; kp < 8; kp++) {
            ull av[8], bv[8];
#pragma unroll
            for (int m = 0; m < 8; m++)
                av[m] = *(const ull*)&As[cur][(ty + 16 * m) * GSA + 2 * kp];
#pragma unroll
            for (int n = 0; n < 8; n++)
                bv[n] = *(const ull*)&Bs[cur][(tx + 16 * n) * GSA + 2 * kp];
#pragma unroll
            for (int m = 0; m < 8; m++)
#pragma unroll
                for (int n = 0; n < 8; n++) ffma2(acc[m][n], av[m], bv[n]);
        }
        if (more) {
            int nxt = cur ^ 1;
            *(float2*)&As[nxt][lr0 * GSA + lc]     = make_float2(pa0.x, pa0.y);
            *(float2*)&As[nxt][lr0 * GSA + lc + 2] = make_float2(pa0.z, pa0.w);
            *(float2*)&As[nxt][lr1 * GSA + lc]     = make_float2(pa1.x, pa1.y);
            *(float2*)&As[nxt][lr1 * GSA + lc + 2] = make_float2(pa1.z, pa1.w);
            *(float2*)&Bs[nxt][lr0 * GSA + lc]     = make_float2(pb0.x, pb0.y);
            *(float2*)&Bs[nxt][lr0 * GSA + lc + 2] = make_float2(pb0.z, pb0.w);
            *(float2*)&Bs[nxt][lr1 * GSA + lc]     = make_float2(pb1.x, pb1.y);
            *(float2*)&Bs[nxt][lr1 * GSA + lc + 2] = make_float2(pb1.z, pb1.w);
            __syncthreads();
            cur = nxt;
        }
    }

    float* dst = g_part + (size_t)blk * 16384;
#pragma unroll
    for (int m = 0; m < 8; m++)
#pragma unroll
        for (int n = 0; n < 8; n++)
            dst[(ty + 16 * m) * 128 + (tx + 16 * n)] = f2sum(acc[m][n]);
}

// ===========================================================================
// Kernel 2b: reduce split-K partials, write G and its mirror
// ===========================================================================
__global__ void gram_reduce() {
    int tile = blockIdx.x;
    int r = tile, bi = 0;
    while (r >= 8 - bi) { r -= 8 - bi; bi++; }
    int bj = bi + r;
    const float* p0 = g_part + (size_t)(0 * 36 + tile) * 16384;
    const float* p1 = g_part + (size_t)(1 * 36 + tile) * 16384;
    const float* p2 = g_part + (size_t)(2 * 36 + tile) * 16384;
    const float* p3 = g_part + (size_t)(3 * 36 + tile) * 16384;
    for (int u = threadIdx.x; u < 16384; u += 256) {
        float s = p0[u] + p1[u] + p2[u] + p3[u];
        int rr = u >> 7, cc = u & 127;
        int i = bi * 128 + rr, j = bj * 128 + cc;
        g_gram[i * N_SAMP + j] = s;
        if (bi != bj) g_gram[j * N_SAMP + i] = s;
    }
}

// ===========================================================================
// Kernel 3: hard mining
// ===========================================================================
__global__ void mine_kernel(const int* __restrict__ targets) {
    int i   = blockIdx.x;
    int tid = threadIdx.x;
    int tg  = targets[i];

    float bpv = -3.0e38f; int bpi = 0;
    float bnv =  3.0e38f; int bni = 0;
    for (int j = tid; j < N_SAMP; j += 256) {
        float val = g_sq[j] - 2.f * g_gram[i * N_SAMP + j];
        if (targets[j] == tg) {
            if (val > bpv || (val == bpv && j < bpi)) { bpv = val; bpi = j; }
        } else {
            if (val < bnv || (val == bnv && j < bni)) { bnv = val; bni = j; }
        }
    }
    __shared__ float spv[256]; __shared__ int spi[256];
    __shared__ float snv[256]; __shared__ int sni[256];
    spv[tid] = bpv; spi[tid] = bpi; snv[tid] = bnv; sni[tid] = bni;
    __syncthreads();
    for (int st = 128; st > 0; st >>= 1) {
        if (tid < st) {
            float ov = spv[tid + st]; int oi = spi[tid + st];
            if (ov > spv[tid] || (ov == spv[tid] && oi < spi[tid])) { spv[tid] = ov; spi[tid] = oi; }
            float nv = snv[tid + st]; int ni2 = sni[tid + st];
            if (nv < snv[tid] || (nv == snv[tid] && ni2 < sni[tid])) { snv[tid] = nv; sni[tid] = ni2; }
        }
        __syncthreads();
    }
    if (tid == 0) { g_hp[i] = spi[0]; g_hn[i] = sni[0]; }
}

// ===========================================================================
// Kernel 4: per-sample cross-attention + distance, FFMA2 GEMMs.
// 256 threads, 8x8 microtile, k-paired dual accumulators.
// Layouts (stride SA=130, conflict-free LDS.64): b1 = A natural -> later O^T;
// b2 = O natural -> later M (stride SM2=132); b3 = S/P natural.
// ===========================================================================
__global__ __launch_bounds__(256, 1)
void attn_kernel(const float* __restrict__ X) {
    extern __shared__ __align__(16) float sm[];
    float* b1 = sm;                  // A natural -> O^T
    float* b2 = sm + 128 * SM2;      // O natural -> M (SM2)
    float* b3 = sm + 2 * 128 * SM2;  // S / P natural
    __shared__ float xch[256];

    const int tid = threadIdx.x;
    const int tx  = tid & 15;       // +16n
    const int ty  = tid >> 4;       // +16m
    const int blk = blockIdx.x;
    const int bb  = blk >> 1;
    const int oidx = (blk & 1) ? g_hn[bb] : g_hp[bb];
    const float* Ag = X + (size_t)bb * D;
    const float* Og = X + (size_t)oidx * D;

    // ---- load A natural -> b1, O natural -> b2 (float2 stores, stride SA) ----
    for (int u = tid; u < 4096; u += 256) {
        int rr = u >> 5;
        int c4 = (u & 31) << 2;
        float4 va = *(const float4*)(Ag + rr * WH + c4);
        float4 vo = *(const float4*)(Og + rr * WH + c4);
        *(float2*)&b1[rr * SA + c4]     = make_float2(va.x, va.y);
        *(float2*)&b1[rr * SA + c4 + 2] = make_float2(va.z, va.w);
        *(float2*)&b2[rr * SA + c4]     = make_float2(vo.x, vo.y);
        *(float2*)&b2[rr * SA + c4 + 2] = make_float2(vo.z, vo.w);
    }
    __syncthreads();

    // ---- GEMM1: S[i][j] = sum_c A[i][c] O[j][c]; i=ty+16m, j=tx+16n ----
    ull acc[8][8];
#pragma unroll
    for (int m = 0; m < 8; m++)
#pragma unroll
        for (int n = 0; n < 8; n++) acc[m][n] = 0ull;

    for (int cp = 0; cp < 64; cp++) {
        ull av[8], bv[8];
#pragma unroll
        for (int m = 0; m < 8; m++)
            av[m] = *(const ull*)&b1[(ty + 16 * m) * SA + 2 * cp];
#pragma unroll
        for (int n = 0; n < 8; n++)
            bv[n] = *(const ull*)&b2[(tx + 16 * n) * SA + 2 * cp];
#pragma unroll
        for (int m = 0; m < 8; m++)
#pragma unroll
            for (int n = 0; n < 8; n++) ffma2(acc[m][n], av[m], bv[n]);
    }
    const float scale = 0.088388347648318447f;  // 1/sqrt(128)
#pragma unroll
    for (int m = 0; m < 8; m++)
#pragma unroll
        for (int n = 0; n < 8; n++)
            b3[(ty + 16 * m) * SA + (tx + 16 * n)] = f2sum(acc[m][n]) * scale;
    __syncthreads();

    // ---- O^T reload into b1 (A dead; dist re-reads A from gmem) ----
    for (int u = tid; u < 4096; u += 256) {
        int rr = u >> 5;
        int c4 = (u & 31) << 2;
        float4 vo = *(const float4*)(Og + rr * WH + c4);
        b1[(c4 + 0) * SA + rr] = vo.x;
        b1[(c4 + 1) * SA + rr] = vo.y;
        b1[(c4 + 2) * SA + rr] = vo.z;
        b1[(c4 + 3) * SA + rr] = vo.w;
    }

    // ---- softmax over rows of S (natural); 2 threads per row ----
    const int ci = tid & 127;
    const int j0 = (tid >> 7) * 64;
    float lmax = -3.0e38f;
    for (int j = j0; j < j0 + 64; j++) lmax = fmaxf(lmax, b3[ci * SA + j]);
    xch[tid] = lmax;
    __syncthreads();
    float gmax = fmaxf(xch[ci], xch[ci + 128]);
    __syncthreads();
    float lsum = 0.f;
    for (int j = j0; j < j0 + 64; j++) {
        float e = __expf(b3[ci * SA + j] - gmax);
        b3[ci * SA + j] = e;
        lsum += e;
    }
    xch[tid] = lsum;
    __syncthreads();
    float rinv = 1.f / (xch[ci] + xch[ci + 128]);
    for (int j = j0; j < j0 + 64; j++) b3[ci * SA + j] *= rinv;
    __syncthreads();  // P ready; O^T (b1) ready

    // ---- GEMM2: M[i][c] = sum_j P[i][j] O[j][c]; i=ty+16m, c=tx+16n ----
#pragma unroll
    for (int m = 0; m < 8; m++)
#pragma unroll
        for (int n = 0; n < 8; n++) acc[m][n] = 0ull;

    for (int jp = 0; jp < 64; jp++) {
        ull pv[8], ov[8];
#pragma unroll
        for (int m = 0; m < 8; m++)
            pv[m] = *(const ull*)&b3[(ty + 16 * m) * SA + 2 * jp];
#pragma unroll
        for (int n = 0; n < 8; n++)
            ov[n] = *(const ull*)&b1[(tx + 16 * n) * SA + 2 * jp];
#pragma unroll
        for (int m = 0; m < 8; m++)
#pragma unroll
            for (int n = 0; n < 8; n++) ffma2(acc[m][n], pv[m], ov[n]);
    }
    __syncthreads();  // b3 reads complete before M overwrites b2 (b2 idle since GEMM1)
#pragma unroll
    for (int m = 0; m < 8; m++)
#pragma unroll
        for (int n = 0; n < 8; n++)
            b2[(ty + 16 * m) * SM2 + (tx + 16 * n)] = f2sum(acc[m][n]);  // M natural @132
    __syncthreads();

    // ---- dist^2 = sum (A - M)^2 ----
    float dsum = 0.f;
    for (int u = tid; u < 4096; u += 256) {
        int rr = u >> 5;
        int c4 = (u & 31) << 2;
        float4 va = *(const float4*)(Ag + rr * WH + c4);
        float4 vm = *(const float4*)(b2 + rr * SM2 + c4);
        float dx = va.x - vm.x, dy = va.y - vm.y;
        float dz = va.z - vm.z, dw = va.w - vm.w;
        dsum += dx * dx + dy * dy + dz * dz + dw * dw;
    }
    xch[tid] = dsum;
    __syncthreads();
    for (int st = 128; st > 0; st >>= 1) {
        if (tid < st) xch[tid] += xch[tid + st];
        __syncthreads();
    }
    if (tid == 0) g_dd[blk] = xch[0];
}

// ===========================================================================
// Kernel 5: final margin ranking loss
// ===========================================================================
__global__ void loss_kernel(float* __restrict__ out) {
    int tid = threadIdx.x;
    float s = 0.f;
    for (int b = tid; b < N_SAMP; b += 256) {
        float dap = sqrtf(g_dd[2 * b]);
        float dan = sqrtf(g_dd[2 * b + 1]);
        float v = dap - dan + 0.3f;
        s += (v > 0.f) ? v : 0.f;
    }
    __shared__ float red[256];
    red[tid] = s;
    __syncthreads();
    for (int st = 128; st > 0; st >>= 1) {
        if (tid < st) red[tid] += red[tid + st];
        __syncthreads();
    }
    if (tid == 0) out[0] = red[0] * (1.0f / (float)N_SAMP);
}

// ===========================================================================
extern "C" void kernel_launch(void* const* d_in, const int* in_sizes, int n_in,
                              void* d_out, int out_size) {
    const float* X;
    const int*   T;
    if (n_in >= 2 && in_sizes[0] == N_SAMP && in_sizes[1] != N_SAMP) {
        T = (const int*)d_in[0];
        X = (const float*)d_in[1];
    } else {
        X = (const float*)d_in[0];
        T = (const int*)d_in[1];
    }

    const int smem_attn = 3 * 128 * SM2 * (int)sizeof(float);  // 202752 B
    cudaFuncSetAttribute(attn_kernel, cudaFuncAttributeMaxDynamicSharedMemorySize,
                         smem_attn);

    sq_kernel<<<N_SAMP, 256>>>(X);
    gram_f2<<<144, 256>>>(X);
    gram_reduce<<<36, 256>>>();
    mine_kernel<<<N_SAMP, 256>>>(T);
    attn_kernel<<<2 * N_SAMP, 256, smem_attn>>>(X);
    loss_kernel<<<1, 256>>>((float*)d_out);
}

// round 9
// speedup vs baseline: 1.4019x; 1.0610x over previous
#include <cuda_runtime.h>
#include <math.h>
#include <stdint.h>

#define N_SAMP 1024
#define D      16384
#define WH     128
#define SA     130   // smem stride (words); 130 % 4 == 2 -> conflict-free LDS.64 column walks
#define GSA    18    // gram stage row stride (words)

typedef unsigned long long ull;

// ---- device scratch (no allocations allowed) ----
__device__ float g_gram[N_SAMP * N_SAMP];
__device__ float g_part[144 * 16384];      // split-K partial tiles
__device__ float g_sq[N_SAMP];
__device__ int   g_hp[N_SAMP];
__device__ int   g_hn[N_SAMP];
__device__ float g_dd[2 * N_SAMP];

// ---- packed fp32x2 FMA (Blackwell dual fp32; exact fp32 math) ----
__device__ __forceinline__ void ffma2(ull& d, ull a, ull b) {
    asm("fma.rn.f32x2 %0, %1, %2, %0;" : "+l"(d) : "l"(a), "l"(b));
}
__device__ __forceinline__ float f2sum(ull v) {
    return __uint_as_float((unsigned)(v & 0xFFFFFFFFu)) +
           __uint_as_float((unsigned)(v >> 32));
}

// ===========================================================================
// Kernel 1: row squared norms
// ===========================================================================
__global__ void sq_kernel(const float* __restrict__ X) {
    int i = blockIdx.x;
    const float4* row = (const float4*)(X + (size_t)i * D);
    float s = 0.f;
    for (int u = threadIdx.x; u < D / 4; u += 256) {
        float4 v = row[u];
        s += v.x * v.x + v.y * v.y + v.z * v.z + v.w * v.w;
    }
    __shared__ float red[256];
    red[threadIdx.x] = s;
    __syncthreads();
    for (int st = 128; st > 0; st >>= 1) {
        if (threadIdx.x < st) red[threadIdx.x] += red[threadIdx.x + st];
        __syncthreads();
    }
    if (threadIdx.x == 0) g_sq[i] = red[0];
}

// ===========================================================================
// Kernel 2: Gram GEMM with FFMA2 (unchanged from R7: at its FFMA2 floor).
// 36 triangular 128x128 tiles x 4 K-splits = 144 blocks (one wave).
// ===========================================================================
__global__ __launch_bounds__(256, 1)
void gram_f2(const float* __restrict__ X) {
    __shared__ __align__(16) float As[2][128 * GSA];
    __shared__ __align__(16) float Bs[2][128 * GSA];

    const int tid = threadIdx.x;
    const int tx  = tid & 15;
    const int ty  = tid >> 4;

    int blk = blockIdx.x;
    int split = blk / 36;
    int tile  = blk % 36;
    int r = tile, bi = 0;
    while (r >= 8 - bi) { r -= 8 - bi; bi++; }
    int bj = bi + r;

    const float* Ag = X + (size_t)(bi * 128) * D + split * 4096;
    const float* Bg = X + (size_t)(bj * 128) * D + split * 4096;

    const int lr0 = tid >> 2;
    const int lr1 = lr0 + 64;
    const int lc  = (tid & 3) << 2;

    ull acc[8][8];
#pragma unroll
    for (int m = 0; m < 8; m++)
#pragma unroll
        for (int n = 0; n < 8; n++) acc[m][n] = 0ull;

    float4 pa0 = *(const float4*)(Ag + (size_t)lr0 * D + lc);
    float4 pa1 = *(const float4*)(Ag + (size_t)lr1 * D + lc);
    float4 pb0 = *(const float4*)(Bg + (size_t)lr0 * D + lc);
    float4 pb1 = *(const float4*)(Bg + (size_t)lr1 * D + lc);
    *(float2*)&As[0][lr0 * GSA + lc]     = make_float2(pa0.x, pa0.y);
    *(float2*)&As[0][lr0 * GSA + lc + 2] = make_float2(pa0.z, pa0.w);
    *(float2*)&As[0][lr1 * GSA + lc]     = make_float2(pa1.x, pa1.y);
    *(float2*)&As[0][lr1 * GSA + lc + 2] = make_float2(pa1.z, pa1.w);
    *(float2*)&Bs[0][lr0 * GSA + lc]     = make_float2(pb0.x, pb0.y);
    *(float2*)&Bs[0][lr0 * GSA + lc + 2] = make_float2(pb0.z, pb0.w);
    *(float2*)&Bs[0][lr1 * GSA + lc]     = make_float2(pb1.x, pb1.y);
    *(float2*)&Bs[0][lr1 * GSA + lc + 2] = make_float2(pb1.z, pb1.w);
    __syncthreads();

    const int NC = 4096 / 16;
    int cur = 0;
    for (int c = 0; c < NC; c++) {
        bool more = (c + 1) < NC;
        if (more) {
            int kk = (c + 1) * 16;
            pa0 = *(const float4*)(Ag + (size_t)lr0 * D + kk + lc);
            pa1 = *(const float4*)(Ag + (size_t)lr1 * D + kk + lc);
            pb0 = *(const float4*)(Bg + (size_t)lr0 * D + kk + lc);
            pb1 = *(const float4*)(Bg + (size_t)lr1 * D + kk + lc);
        }
#pragma unroll
        for (int kp = 0; kp < 8; kp++) {
            ull av[8], bv[8];
#pragma unroll
            for (int m = 0; m < 8; m++)
                av[m] = *(const ull*)&As[cur][(ty + 16 * m) * GSA + 2 * kp];
#pragma unroll
            for (int n = 0; n < 8; n++)
                bv[n] = *(const ull*)&Bs[cur][(tx + 16 * n) * GSA + 2 * kp];
#pragma unroll
            for (int m = 0; m < 8; m++)
#pragma unroll
                for (int n = 0; n < 8; n++) ffma2(acc[m][n], av[m], bv[n]);
        }
        if (more) {
            int nxt = cur ^ 1;
            *(float2*)&As[nxt][lr0 * GSA + lc]     = make_float2(pa0.x, pa0.y);
            *(float2*)&As[nxt][lr0 * GSA + lc + 2] = make_float2(pa0.z, pa0.w);
            *(float2*)&As[nxt][lr1 * GSA + lc]     = make_float2(pa1.x, pa1.y);
            *(float2*)&As[nxt][lr1 * GSA + lc + 2] = make_float2(pa1.z, pa1.w);
            *(float2*)&Bs[nxt][lr0 * GSA + lc]     = make_float2(pb0.x, pb0.y);
            *(float2*)&Bs[nxt][lr0 * GSA + lc + 2] = make_float2(pb0.z, pb0.w);
            *(float2*)&Bs[nxt][lr1 * GSA + lc]     = make_float2(pb1.x, pb1.y);
            *(float2*)&Bs[nxt][lr1 * GSA + lc + 2] = make_float2(pb1.z, pb1.w);
            __syncthreads();
            cur = nxt;
        }
    }

    float* dst = g_part + (size_t)blk * 16384;
#pragma unroll
    for (int m = 0; m < 8; m++)
#pragma unroll
        for (int n = 0; n < 8; n++)
            dst[(ty + 16 * m) * 128 + (tx + 16 * n)] = f2sum(acc[m][n]);
}

// ===========================================================================
// Kernel 2b: reduce split-K partials, write G and its mirror
// ===========================================================================
__global__ void gram_reduce() {
    int tile = blockIdx.x;
    int r = tile, bi = 0;
    while (r >= 8 - bi) { r -= 8 - bi; bi++; }
    int bj = bi + r;
    const float* p0 = g_part + (size_t)(0 * 36 + tile) * 16384;
    const float* p1 = g_part + (size_t)(1 * 36 + tile) * 16384;
    const float* p2 = g_part + (size_t)(2 * 36 + tile) * 16384;
    const float* p3 = g_part + (size_t)(3 * 36 + tile) * 16384;
    for (int u = threadIdx.x; u < 16384; u += 256) {
        float s = p0[u] + p1[u] + p2[u] + p3[u];
        int rr = u >> 7, cc = u & 127;
        int i = bi * 128 + rr, j = bj * 128 + cc;
        g_gram[i * N_SAMP + j] = s;
        if (bi != bj) g_gram[j * N_SAMP + i] = s;
    }
}

// ===========================================================================
// Kernel 3: hard mining
// ===========================================================================
__global__ void mine_kernel(const int* __restrict__ targets) {
    int i   = blockIdx.x;
    int tid = threadIdx.x;
    int tg  = targets[i];

    float bpv = -3.0e38f; int bpi = 0;
    float bnv =  3.0e38f; int bni = 0;
    for (int j = tid; j < N_SAMP; j += 256) {
        float val = g_sq[j] - 2.f * g_gram[i * N_SAMP + j];
        if (targets[j] == tg) {
            if (val > bpv || (val == bpv && j < bpi)) { bpv = val; bpi = j; }
        } else {
            if (val < bnv || (val == bnv && j < bni)) { bnv = val; bni = j; }
        }
    }
    __shared__ float spv[256]; __shared__ int spi[256];
    __shared__ float snv[256]; __shared__ int sni[256];
    spv[tid] = bpv; spi[tid] = bpi; snv[tid] = bnv; sni[tid] = bni;
    __syncthreads();
    for (int st = 128; st > 0; st >>= 1) {
        if (tid < st) {
            float ov = spv[tid + st]; int oi = spi[tid + st];
            if (ov > spv[tid] || (ov == spv[tid] && oi < spi[tid])) { spv[tid] = ov; spi[tid] = oi; }
            float nv = snv[tid + st]; int ni2 = sni[tid + st];
            if (nv < snv[tid] || (nv == snv[tid] && ni2 < sni[tid])) { snv[tid] = nv; sni[tid] = ni2; }
        }
        __syncthreads();
    }
    if (tid == 0) { g_hp[i] = spi[0]; g_hn[i] = sni[0]; }
}

// ===========================================================================
// Kernel 4: attention + distance. 512 threads (16 warps), 4x8 microtile,
// FFMA2, REGISTER softmax (half-warp shuffles), fused distance epilogue.
// Only 2 smem buffers: b1 = A natural -> P natural; b2 = O natural -> O^T.
// ===========================================================================
__global__ __launch_bounds__(512, 1)
void attn_kernel(const float* __restrict__ X) {
    extern __shared__ __align__(16) float sm[];
    float* b1 = sm;              // A natural -> P natural
    float* b2 = sm + 128 * SA;   // O natural -> O^T
    __shared__ float xch[512];

    const int tid = threadIdx.x;
    const int tx  = tid & 15;       // j/c index: tx + 16n, n<8
    const int ty  = tid >> 4;       // i index:   ty + 32m, m<4
    const int blk = blockIdx.x;
    const int bb  = blk >> 1;
    const int oidx = (blk & 1) ? g_hn[bb] : g_hp[bb];
    const float* Ag = X + (size_t)bb * D;
    const float* Og = X + (size_t)oidx * D;

    // ---- phase 1: A natural -> b1, O natural -> b2 ----
    for (int u = tid; u < 4096; u += 512) {
        int rr = u >> 5;
        int c4 = (u & 31) << 2;
        float4 va = *(const float4*)(Ag + rr * WH + c4);
        float4 vo = *(const float4*)(Og + rr * WH + c4);
        *(float2*)&b1[rr * SA + c4]     = make_float2(va.x, va.y);
        *(float2*)&b1[rr * SA + c4 + 2] = make_float2(va.z, va.w);
        *(float2*)&b2[rr * SA + c4]     = make_float2(vo.x, vo.y);
        *(float2*)&b2[rr * SA + c4 + 2] = make_float2(vo.z, vo.w);
    }
    __syncthreads();

    // ---- phase 2: GEMM1  S[i][j] = sum_c A[i][c] O[j][c] ----
    ull acc[4][8];
#pragma unroll
    for (int m = 0; m < 4; m++)
#pragma unroll
        for (int n = 0; n < 8; n++) acc[m][n] = 0ull;

    for (int cp = 0; cp < 64; cp++) {
        ull av[4], bv[8];
#pragma unroll
        for (int m = 0; m < 4; m++)
            av[m] = *(const ull*)&b1[(ty + 32 * m) * SA + 2 * cp];
#pragma unroll
        for (int n = 0; n < 8; n++)
            bv[n] = *(const ull*)&b2[(tx + 16 * n) * SA + 2 * cp];
#pragma unroll
        for (int m = 0; m < 4; m++)
#pragma unroll
            for (int n = 0; n < 8; n++) ffma2(acc[m][n], av[m], bv[n]);
    }

    // ---- phase 3: register softmax along j (16 threads/row = half-warp) ----
    const float scale = 0.088388347648318447f;  // 1/sqrt(128)
    float p[4][8];
#pragma unroll
    for (int m = 0; m < 4; m++) {
        float rmax = -3.0e38f;
#pragma unroll
        for (int n = 0; n < 8; n++) {
            p[m][n] = f2sum(acc[m][n]) * scale;
            rmax = fmaxf(rmax, p[m][n]);
        }
#pragma unroll
        for (int s = 1; s < 16; s <<= 1)
            rmax = fmaxf(rmax, __shfl_xor_sync(0xFFFFFFFFu, rmax, s));
        float rsum = 0.f;
#pragma unroll
        for (int n = 0; n < 8; n++) {
            p[m][n] = __expf(p[m][n] - rmax);
            rsum += p[m][n];
        }
#pragma unroll
        for (int s = 1; s < 16; s <<= 1)
            rsum += __shfl_xor_sync(0xFFFFFFFFu, rsum, s);
        float rinv = 1.f / rsum;
#pragma unroll
        for (int n = 0; n < 8; n++) p[m][n] *= rinv;
    }
    __syncthreads();  // all GEMM1 smem reads done before overwrite

    // ---- phase 4: write P natural -> b1; rewrite b2 as O^T from gmem ----
#pragma unroll
    for (int m = 0; m < 4; m++)
#pragma unroll
        for (int n = 0; n < 8; n++)
            b1[(ty + 32 * m) * SA + tx + 16 * n] = p[m][n];
    for (int u = tid; u < 4096; u += 512) {
        int rr = u >> 5;
        int c4 = (u & 31) << 2;
        float4 vo = *(const float4*)(Og + rr * WH + c4);
        b2[(c4 + 0) * SA + rr] = vo.x;
        b2[(c4 + 1) * SA + rr] = vo.y;
        b2[(c4 + 2) * SA + rr] = vo.z;
        b2[(c4 + 3) * SA + rr] = vo.w;
    }
    __syncthreads();

    // ---- phase 5: GEMM2  M[i][c] = sum_j P[i][j] O[j][c]  (O^T in b2) ----
    ull acc2[4][8];
#pragma unroll
    for (int m = 0; m < 4; m++)
#pragma unroll
        for (int n = 0; n < 8; n++) acc2[m][n] = 0ull;

    for (int jp = 0; jp < 64; jp++) {
        ull pv[4], ov[8];
#pragma unroll
        for (int m = 0; m < 4; m++)
            pv[m] = *(const ull*)&b1[(ty + 32 * m) * SA + 2 * jp];
#pragma unroll
        for (int n = 0; n < 8; n++)
            ov[n] = *(const ull*)&b2[(tx + 16 * n) * SA + 2 * jp];
#pragma unroll
        for (int m = 0; m < 4; m++)
#pragma unroll
            for (int n = 0; n < 8; n++) ffma2(acc2[m][n], pv[m], ov[n]);
    }

    // ---- phase 6: fused distance (A from gmem, L2-hot) + block reduce ----
    float dsum = 0.f;
#pragma unroll
    for (int m = 0; m < 4; m++)
#pragma unroll
        for (int n = 0; n < 8; n++) {
            float a = Ag[(ty + 32 * m) * WH + tx + 16 * n];
            float d = a - f2sum(acc2[m][n]);
            dsum += d * d;
        }
    xch[tid] = dsum;
    __syncthreads();
    for (int st = 256; st > 0; st >>= 1) {
        if (tid < st) xch[tid] += xch[tid + st];
        __syncthreads();
    }
    if (tid == 0) g_dd[blk] = xch[0];
}

// ===========================================================================
// Kernel 5: final margin ranking loss
// ===========================================================================
__global__ void loss_kernel(float* __restrict__ out) {
    int tid = threadIdx.x;
    float s = 0.f;
    for (int b = tid; b < N_SAMP; b += 256) {
        float dap = sqrtf(g_dd[2 * b]);
        float dan = sqrtf(g_dd[2 * b + 1]);
        float v = dap - dan + 0.3f;
        s += (v > 0.f) ? v : 0.f;
    }
    __shared__ float red[256];
    red[tid] = s;
    __syncthreads();
    for (int st = 128; st > 0; st >>= 1) {
        if (tid < st) red[tid] += red[tid + st];
        __syncthreads();
    }
    if (tid == 0) out[0] = red[0] * (1.0f / (float)N_SAMP);
}

// ===========================================================================
extern "C" void kernel_launch(void* const* d_in, const int* in_sizes, int n_in,
                              void* d_out, int out_size) {
    const float* X;
    const int*   T;
    if (n_in >= 2 && in_sizes[0] == N_SAMP && in_sizes[1] != N_SAMP) {
        T = (const int*)d_in[0];
        X = (const float*)d_in[1];
    } else {
        X = (const float*)d_in[0];
        T = (const int*)d_in[1];
    }

    const int smem_attn = 2 * 128 * SA * (int)sizeof(float);  // 133120 B
    cudaFuncSetAttribute(attn_kernel, cudaFuncAttributeMaxDynamicSharedMemorySize,
                         smem_attn);

    sq_kernel<<<N_SAMP, 256>>>(X);
    gram_f2<<<144, 256>>>(X);
    gram_reduce<<<36, 256>>>();
    mine_kernel<<<N_SAMP, 256>>>(T);
    attn_kernel<<<2 * N_SAMP, 512, smem_attn>>>(X);
    loss_kernel<<<1, 256>>>((float*)d_out);
}